// round 14
// baseline (speedup 1.0000x reference)
#include <cuda_runtime.h>
#include <cuda_fp16.h>

// LogicDense: out[i][j] = c0 + c1*a + c2*b + c3*a*b
//   a = x[i, idx0[j]], b = x[i, idx1[j]]
//
// R14 vs R13 (main stuck at 38.7 us; no single pipe binding):
//  - ROWS 8 -> 16: each block stages TWO 64 KiB fp16 sub-tiles (rows 0-7 and
//    8-15 of a 16-row group). One table record (cf uint4 + of uint2) now
//    serves 16 rows -> table LTS traffic and record loads per output HALVED
//    (48 -> 24 MiB). Same u16 swizzled offsets valid in both sub-tiles.
//  - 1024 threads, 1 block/SM (128 KiB smem), occ 50% (up from 42%).
//    Tile0 gathers die before tile1 loads -> ~45 live regs, under the 64 cap.
//  - Keeps: PDL overlap of precompute, slim 24 B/pair table, record prefetch,
//    STG.64 column-pair stores, swizzled fp16 tile.

#define ROWSH   8            // rows per sub-tile
#define ROWS    16           // rows per block group
#define THREADS 1024
#define MAX_OUT 16384

__device__ uint4 g_cf[MAX_OUT / 2];   // per-pair coeffs: h2(c0,c1)E, h2(c2,c3)E, h2(c0,c1)O, h2(c2,c3)O
__device__ uint2 g_of[MAX_OUT / 2];   // per-pair offsets: (offAE|offBE<<16, offAO|offBO<<16)

__constant__ float c_T[64] = {
    0.f, 0.f, 0.f, 0.f,
    0.f, 0.f, 0.f, 1.f,
    0.f, 1.f, 0.f,-1.f,
    0.f, 1.f, 0.f, 0.f,
    0.f, 0.f, 1.f,-1.f,
    0.f, 0.f, 1.f, 0.f,
    0.f, 1.f, 1.f,-2.f,
    0.f, 1.f, 1.f,-1.f,
    1.f,-1.f,-1.f, 1.f,
    1.f,-1.f,-1.f, 2.f,
    1.f, 0.f,-1.f, 0.f,
    1.f, 0.f,-1.f, 1.f,
    1.f,-1.f, 0.f, 0.f,
    1.f,-1.f, 0.f, 1.f,
    1.f, 0.f, 0.f,-1.f,
    1.f, 0.f, 0.f, 0.f
};

__device__ __forceinline__ int swz_off(int idx) {
    // half-index of the 8-row group of element idx in a swizzled sub-tile
    return (idx << 3) ^ (((idx >> 3) & 7) << 3);
}

__device__ __forceinline__ void softmax_coef(const float* __restrict__ w, int col,
                                             unsigned int& c01u, unsigned int& c23u) {
    const float4* w4 = (const float4*)(w + (size_t)col * 16);
    float4 wa = w4[0], wb = w4[1], wc = w4[2], wd = w4[3];
    float wv[16] = {wa.x, wa.y, wa.z, wa.w, wb.x, wb.y, wb.z, wb.w,
                    wc.x, wc.y, wc.z, wc.w, wd.x, wd.y, wd.z, wd.w};
    float m = -1e30f;
#pragma unroll
    for (int k = 0; k < 16; k++) m = fmaxf(m, wv[k]);
    float s = 0.f;
#pragma unroll
    for (int k = 0; k < 16; k++) {
        wv[k] = __expf(wv[k] - m);
        s += wv[k];
    }
    float inv = 1.f / s;
    float c0 = 0.f, c1 = 0.f, c2 = 0.f, c3 = 0.f;
#pragma unroll
    for (int k = 0; k < 16; k++) {
        float p = wv[k] * inv;
        c0 = fmaf(p, c_T[4 * k + 0], c0);
        c1 = fmaf(p, c_T[4 * k + 1], c1);
        c2 = fmaf(p, c_T[4 * k + 2], c2);
        c3 = fmaf(p, c_T[4 * k + 3], c3);
    }
    __half2 c01 = __floats2half2_rn(c0, c1);
    __half2 c23 = __floats2half2_rn(c2, c3);
    c01u = *(unsigned int*)&c01;
    c23u = *(unsigned int*)&c23;
}

__global__ void precompute_kernel(const void* __restrict__ idx_raw,
                                  const float* __restrict__ w,
                                  int out_dim) {
    // dtype detect: odd u32 words of the first 64 words are all zero iff the
    // buffer is int64 (high words of indices < in_dim). Warp-ballot, no smem.
    const unsigned int* u = (const unsigned int*)idx_raw;
    unsigned int probe = u[2 * (threadIdx.x & 31) + 1];
    const int is64 = !__any_sync(0xFFFFFFFFu, probe != 0u);

    const int npair = out_dim >> 1;
    int q = blockIdx.x * blockDim.x + threadIdx.x;   // pair index
    if (q >= npair) return;
    const int jE = 2 * q, jO = 2 * q + 1;

    uint4 cf;
    softmax_coef(w, jE, cf.x, cf.y);
    softmax_coef(w, jO, cf.z, cf.w);
    g_cf[q] = cf;

    int aE, bE, aO, bO;
    if (is64) {
        const long long* p = (const long long*)idx_raw;
        aE = (int)p[jE]; bE = (int)p[out_dim + jE];
        aO = (int)p[jO]; bO = (int)p[out_dim + jO];
    } else {
        const int* p = (const int*)idx_raw;
        aE = p[jE]; bE = p[out_dim + jE];
        aO = p[jO]; bO = p[out_dim + jO];
    }
    uint2 of;
    of.x = (unsigned int)swz_off(aE) | ((unsigned int)swz_off(bE) << 16);
    of.y = (unsigned int)swz_off(aO) | ((unsigned int)swz_off(bO) << 16);
    g_of[q] = of;
}

__device__ __forceinline__ unsigned int pack_h2(float lo, float hi) {
    __half2 h = __floats2half2_rn(lo, hi);
    return *(unsigned int*)&h;
}

__device__ __forceinline__ float2 h22f2(unsigned int u) {
    return __half22float2(*(const __half2*)&u);
}

template <bool FULL>
__global__ __launch_bounds__(THREADS) void logic_main_kernel(
    const float* __restrict__ x,
    float* __restrict__ out,
    int in_dim, int out_dim, int batch) {
    extern __shared__ __half sh[];   // 2 sub-tiles of in_dim*8 halfs (128 KiB)

    const int rb = blockIdx.x * ROWS;
    const int tile_halfs = in_dim * ROWSH;

    // ---- stage 16 rows as two swizzled fp16 sub-tiles (needs only x) ----
    {
        const int n4 = in_dim >> 2;   // element-chunks of 4
#pragma unroll
        for (int t = 0; t < 2; t++) {
            __half* shp = sh + t * tile_halfs;
            const int rt = rb + t * ROWSH;
            const float* xb = x + (size_t)rt * in_dim;
            for (int i = threadIdx.x; i < n4; i += blockDim.x) {
                float4 r[ROWSH];
#pragma unroll
                for (int rr = 0; rr < ROWSH; rr++) {
                    int row = (FULL || rt + rr < batch) ? rr : 0;
                    r[rr] = *(const float4*)(xb + (size_t)row * in_dim + (i << 2));
                }
#pragma unroll
                for (int k = 0; k < 4; k++) {
                    uint4 pk;
                    pk.x = pack_h2((&r[0].x)[k], (&r[1].x)[k]);
                    pk.y = pack_h2((&r[2].x)[k], (&r[3].x)[k]);
                    pk.z = pack_h2((&r[4].x)[k], (&r[5].x)[k]);
                    pk.w = pack_h2((&r[6].x)[k], (&r[7].x)[k]);
                    *(uint4*)(shp + swz_off((i << 2) + k)) = pk;
                }
            }
        }
    }
    __syncthreads();

    // PDL: precompute's table writes must be visible before the compute loop.
    cudaGridDependencySynchronize();

    // ---- compute: one record read serves 16 rows (both sub-tiles) ----
    const int npair = out_dim >> 1;
    int q = threadIdx.x;
    if (q < npair) {
        uint4 cf = g_cf[q];
        uint2 of = g_of[q];
        while (true) {
            const int qn = q + (int)blockDim.x;
            uint4 cfn; uint2 ofn;
            const bool more = (qn < npair);
            if (more) {             // prefetch next record before computing
                cfn = g_cf[qn];
                ofn = g_of[qn];
            }

            const float2 cE01 = h22f2(cf.x);
            const float2 cE23 = h22f2(cf.y);
            const float2 cO01 = h22f2(cf.z);
            const float2 cO23 = h22f2(cf.w);

            float* opb = out + (size_t)rb * out_dim + 2 * q;
#pragma unroll
            for (int t = 0; t < 2; t++) {
                const __half* shp = sh + t * tile_halfs;
                const int rt = t * ROWSH;

                const uint4 aE = *(const uint4*)(shp + (of.x & 0xFFFFu));
                const uint4 bE = *(const uint4*)(shp + (of.x >> 16));
                const uint4 aO = *(const uint4*)(shp + (of.y & 0xFFFFu));
                const uint4 bO = *(const uint4*)(shp + (of.y >> 16));

#pragma unroll
                for (int r2 = 0; r2 < 4; r2++) {
                    const float2 vaE = h22f2((&aE.x)[r2]);
                    const float2 vbE = h22f2((&bE.x)[r2]);
                    const float2 vaO = h22f2((&aO.x)[r2]);
                    const float2 vbO = h22f2((&bO.x)[r2]);

                    const int r0 = rt + 2 * r2;
                    if (FULL || rb + r0 < batch) {
                        float2 res;
                        res.x = fmaf(vaE.x, fmaf(vbE.x, cE23.y, cE01.y),
                                     fmaf(vbE.x, cE23.x, cE01.x));
                        res.y = fmaf(vaO.x, fmaf(vbO.x, cO23.y, cO01.y),
                                     fmaf(vbO.x, cO23.x, cO01.x));
                        *(float2*)(opb + (size_t)r0 * out_dim) = res;
                    }
                    if (FULL || rb + r0 + 1 < batch) {
                        float2 res;
                        res.x = fmaf(vaE.y, fmaf(vbE.y, cE23.y, cE01.y),
                                     fmaf(vbE.y, cE23.x, cE01.x));
                        res.y = fmaf(vaO.y, fmaf(vbO.y, cO23.y, cO01.y),
                                     fmaf(vbO.y, cO23.x, cO01.x));
                        *(float2*)(opb + (size_t)(r0 + 1) * out_dim) = res;
                    }
                }
            }

            if (!more) break;
            q = qn;
            cf = cfn;
            of = ofn;
        }
    }
}

template <bool FULL>
static void launch_main_pdl(const float* x, float* out,
                            int in_dim, int out_dim, int batch,
                            int grid, size_t smem) {
    cudaFuncSetAttribute(logic_main_kernel<FULL>,
                         cudaFuncAttributeMaxDynamicSharedMemorySize, (int)smem);
    cudaLaunchConfig_t cfg = {};
    cfg.gridDim = dim3((unsigned)grid, 1, 1);
    cfg.blockDim = dim3(THREADS, 1, 1);
    cfg.dynamicSmemBytes = smem;
    cudaLaunchAttribute attr[1];
    attr[0].id = cudaLaunchAttributeProgrammaticStreamSerialization;
    attr[0].val.programmaticStreamSerializationAllowed = 1;
    cfg.attrs = attr;
    cfg.numAttrs = 1;
    cudaLaunchKernelEx(&cfg, logic_main_kernel<FULL>,
                       x, out, in_dim, out_dim, batch);
}

extern "C" void kernel_launch(void* const* d_in, const int* in_sizes, int n_in,
                              void* d_out, int out_size) {
    const float* x   = (const float*)d_in[0];
    const void*  idx = d_in[1];
    const float* w   = (const float*)d_in[2];
    float*       out = (float*)d_out;

    const int out_dim = in_sizes[2] / 16;         // weight is (out_dim, 16)
    const int batch   = out_size / out_dim;       // out is (batch, out_dim)
    const int in_dim  = in_sizes[0] / batch;      // x is (batch, in_dim)

    const int npair = out_dim >> 1;
    precompute_kernel<<<(npair + 255) / 256, 256>>>(idx, w, out_dim);

    const size_t smem = (size_t)in_dim * ROWS * sizeof(__half);   // 128 KiB @ 4096
    const int grid = (batch + ROWS - 1) / ROWS;

    if (batch % ROWS == 0)
        launch_main_pdl<true>(x, out, in_dim, out_dim, batch, grid, smem);
    else
        launch_main_pdl<false>(x, out, in_dim, out_dim, batch, grid, smem);
}

// round 15
// speedup vs baseline: 1.0359x; 1.0359x over previous
#include <cuda_runtime.h>
#include <cuda_fp16.h>

// LogicDense: out[i][j] = c0 + c1*a + c2*b + c3*a*b
//   a = x[i, idx0[j]], b = x[i, idx1[j]]
//
// R15 = R13 (best total 45.4 us; main 38.7) + gap-directed tweaks.
// Evidence R11/R13/R14: three different designs all hit main ~38.6 us while
// table traffic went 64 -> 48 -> 24 MiB => main is at its compulsory-DRAM
// floor (~201 MB mixed r/w). Remaining target: the 6.7 us total-main gap.
//  1) precompute calls cudaTriggerProgrammaticLaunchCompletion() right after
//     its table stores -> PDL dependency releases before kernel teardown.
//  2) precompute sized to exactly npair threads (128-thr blocks) to minimize
//     residency contention with PDL-overlapped main blocks.
// ROWS=16 (R14) rejected: same main, larger gap -> total regressed.

#define ROWS 8
#define THREADS 512
#define MAX_OUT 16384

__device__ uint4 g_cf[MAX_OUT / 2];   // per-pair coeffs: h2(c0,c1)E, h2(c2,c3)E, h2(c0,c1)O, h2(c2,c3)O
__device__ uint2 g_of[MAX_OUT / 2];   // per-pair offsets: (offAE|offBE<<16, offAO|offBO<<16)

__constant__ float c_T[64] = {
    0.f, 0.f, 0.f, 0.f,
    0.f, 0.f, 0.f, 1.f,
    0.f, 1.f, 0.f,-1.f,
    0.f, 1.f, 0.f, 0.f,
    0.f, 0.f, 1.f,-1.f,
    0.f, 0.f, 1.f, 0.f,
    0.f, 1.f, 1.f,-2.f,
    0.f, 1.f, 1.f,-1.f,
    1.f,-1.f,-1.f, 1.f,
    1.f,-1.f,-1.f, 2.f,
    1.f, 0.f,-1.f, 0.f,
    1.f, 0.f,-1.f, 1.f,
    1.f,-1.f, 0.f, 0.f,
    1.f,-1.f, 0.f, 1.f,
    1.f, 0.f, 0.f,-1.f,
    1.f, 0.f, 0.f, 0.f
};

__device__ __forceinline__ int swz_off(int idx) {
    // half-index of the 8-row group of element idx in the swizzled tile
    return (idx << 3) ^ (((idx >> 3) & 7) << 3);
}

__device__ __forceinline__ void softmax_coef(const float* __restrict__ w, int col,
                                             unsigned int& c01u, unsigned int& c23u) {
    const float4* w4 = (const float4*)(w + (size_t)col * 16);
    float4 wa = w4[0], wb = w4[1], wc = w4[2], wd = w4[3];
    float wv[16] = {wa.x, wa.y, wa.z, wa.w, wb.x, wb.y, wb.z, wb.w,
                    wc.x, wc.y, wc.z, wc.w, wd.x, wd.y, wd.z, wd.w};
    float m = -1e30f;
#pragma unroll
    for (int k = 0; k < 16; k++) m = fmaxf(m, wv[k]);
    float s = 0.f;
#pragma unroll
    for (int k = 0; k < 16; k++) {
        wv[k] = __expf(wv[k] - m);
        s += wv[k];
    }
    float inv = 1.f / s;
    float c0 = 0.f, c1 = 0.f, c2 = 0.f, c3 = 0.f;
#pragma unroll
    for (int k = 0; k < 16; k++) {
        float p = wv[k] * inv;
        c0 = fmaf(p, c_T[4 * k + 0], c0);
        c1 = fmaf(p, c_T[4 * k + 1], c1);
        c2 = fmaf(p, c_T[4 * k + 2], c2);
        c3 = fmaf(p, c_T[4 * k + 3], c3);
    }
    __half2 c01 = __floats2half2_rn(c0, c1);
    __half2 c23 = __floats2half2_rn(c2, c3);
    c01u = *(unsigned int*)&c01;
    c23u = *(unsigned int*)&c23;
}

__global__ void precompute_kernel(const void* __restrict__ idx_raw,
                                  const float* __restrict__ w,
                                  int out_dim) {
    // dtype detect: odd u32 words of the first 64 words are all zero iff the
    // buffer is int64 (high words of indices < in_dim). Warp-ballot, no smem.
    const unsigned int* u = (const unsigned int*)idx_raw;
    unsigned int probe = u[2 * (threadIdx.x & 31) + 1];
    const int is64 = !__any_sync(0xFFFFFFFFu, probe != 0u);

    const int npair = out_dim >> 1;
    int q = blockIdx.x * blockDim.x + threadIdx.x;   // pair index
    if (q < npair) {
        const int jE = 2 * q, jO = 2 * q + 1;

        uint4 cf;
        softmax_coef(w, jE, cf.x, cf.y);
        softmax_coef(w, jO, cf.z, cf.w);
        g_cf[q] = cf;

        int aE, bE, aO, bO;
        if (is64) {
            const long long* p = (const long long*)idx_raw;
            aE = (int)p[jE]; bE = (int)p[out_dim + jE];
            aO = (int)p[jO]; bO = (int)p[out_dim + jO];
        } else {
            const int* p = (const int*)idx_raw;
            aE = p[jE]; bE = p[out_dim + jE];
            aO = p[jO]; bO = p[out_dim + jO];
        }
        uint2 of;
        of.x = (unsigned int)swz_off(aE) | ((unsigned int)swz_off(bE) << 16);
        of.y = (unsigned int)swz_off(aO) | ((unsigned int)swz_off(bO) << 16);
        g_of[q] = of;
    }
    // Release the PDL dependency as early as possible (stores issued above).
    cudaTriggerProgrammaticLaunchCompletion();
}

__device__ __forceinline__ unsigned int pack_h2(float lo, float hi) {
    __half2 h = __floats2half2_rn(lo, hi);
    return *(unsigned int*)&h;
}

__device__ __forceinline__ float2 h22f2(unsigned int u) {
    return __half22float2(*(const __half2*)&u);
}

template <bool FULL>
__global__ __launch_bounds__(THREADS) void logic_main_kernel(
    const float* __restrict__ x,
    float* __restrict__ out,
    int in_dim, int out_dim, int batch) {
    extern __shared__ __half sh[];   // in_dim * 8 halfs (64 KiB @ 4096), swizzled

    const int rb = blockIdx.x * ROWS;
    const int nr = FULL ? ROWS : min(ROWS, batch - rb);

    // ---- stage 8 rows (independent of the table -> overlaps precompute) ----
    {
        const int n4 = in_dim >> 2;   // element-chunks of 4
        const float* xb = x + (size_t)rb * in_dim;
        for (int i = threadIdx.x; i < n4; i += blockDim.x) {
            float4 r[ROWS];
#pragma unroll
            for (int rr = 0; rr < ROWS; rr++) {
                int row = (FULL || rr < nr) ? rr : 0;
                r[rr] = *(const float4*)(xb + (size_t)row * in_dim + (i << 2));
            }
#pragma unroll
            for (int k = 0; k < 4; k++) {
                uint4 pk;
                pk.x = pack_h2((&r[0].x)[k], (&r[1].x)[k]);
                pk.y = pack_h2((&r[2].x)[k], (&r[3].x)[k]);
                pk.z = pack_h2((&r[4].x)[k], (&r[5].x)[k]);
                pk.w = pack_h2((&r[6].x)[k], (&r[7].x)[k]);
                const int idx = (i << 2) + k;
                *(uint4*)(sh + swz_off(idx)) = pk;
            }
        }
    }
    __syncthreads();

    // PDL: precompute's table writes must be visible before the compute loop.
    cudaGridDependencySynchronize();

    // ---- compute: column pair per thread, records prefetched 1 iter ahead ----
    const int npair = out_dim >> 1;
    int q = threadIdx.x;
    if (q < npair) {
        uint4 cf = g_cf[q];
        uint2 of = g_of[q];
        while (true) {
            const int qn = q + (int)blockDim.x;
            uint4 cfn; uint2 ofn;
            const bool more = (qn < npair);
            if (more) {             // prefetch next records before computing
                cfn = g_cf[qn];
                ofn = g_of[qn];
            }

            const uint4 aE = *(const uint4*)(sh + (of.x & 0xFFFFu));
            const uint4 bE = *(const uint4*)(sh + (of.x >> 16));
            const uint4 aO = *(const uint4*)(sh + (of.y & 0xFFFFu));
            const uint4 bO = *(const uint4*)(sh + (of.y >> 16));

            const float2 cE01 = h22f2(cf.x);
            const float2 cE23 = h22f2(cf.y);
            const float2 cO01 = h22f2(cf.z);
            const float2 cO23 = h22f2(cf.w);

            float* op = out + (size_t)rb * out_dim + 2 * q;
#pragma unroll
            for (int r2 = 0; r2 < 4; r2++) {
                const float2 vaE = h22f2((&aE.x)[r2]);
                const float2 vbE = h22f2((&bE.x)[r2]);
                const float2 vaO = h22f2((&aO.x)[r2]);
                const float2 vbO = h22f2((&bO.x)[r2]);

                // row 2*r2
                if (FULL || 2 * r2 < nr) {
                    float2 res;
                    res.x = fmaf(vaE.x, fmaf(vbE.x, cE23.y, cE01.y),
                                 fmaf(vbE.x, cE23.x, cE01.x));
                    res.y = fmaf(vaO.x, fmaf(vbO.x, cO23.y, cO01.y),
                                 fmaf(vbO.x, cO23.x, cO01.x));
                    *(float2*)(op + (size_t)(2 * r2) * out_dim) = res;
                }
                // row 2*r2+1
                if (FULL || 2 * r2 + 1 < nr) {
                    float2 res;
                    res.x = fmaf(vaE.y, fmaf(vbE.y, cE23.y, cE01.y),
                                 fmaf(vbE.y, cE23.x, cE01.x));
                    res.y = fmaf(vaO.y, fmaf(vbO.y, cO23.y, cO01.y),
                                 fmaf(vbO.y, cO23.x, cO01.x));
                    *(float2*)(op + (size_t)(2 * r2 + 1) * out_dim) = res;
                }
            }

            if (!more) break;
            q = qn;
            cf = cfn;
            of = ofn;
        }
    }
}

template <bool FULL>
static void launch_main_pdl(const float* x, float* out,
                            int in_dim, int out_dim, int batch,
                            int grid, size_t smem) {
    cudaFuncSetAttribute(logic_main_kernel<FULL>,
                         cudaFuncAttributeMaxDynamicSharedMemorySize, (int)smem);
    cudaLaunchConfig_t cfg = {};
    cfg.gridDim = dim3((unsigned)grid, 1, 1);
    cfg.blockDim = dim3(THREADS, 1, 1);
    cfg.dynamicSmemBytes = smem;
    cudaLaunchAttribute attr[1];
    attr[0].id = cudaLaunchAttributeProgrammaticStreamSerialization;
    attr[0].val.programmaticStreamSerializationAllowed = 1;
    cfg.attrs = attr;
    cfg.numAttrs = 1;
    cudaLaunchKernelEx(&cfg, logic_main_kernel<FULL>,
                       x, out, in_dim, out_dim, batch);
}

extern "C" void kernel_launch(void* const* d_in, const int* in_sizes, int n_in,
                              void* d_out, int out_size) {
    const float* x   = (const float*)d_in[0];
    const void*  idx = d_in[1];
    const float* w   = (const float*)d_in[2];
    float*       out = (float*)d_out;

    const int out_dim = in_sizes[2] / 16;         // weight is (out_dim, 16)
    const int batch   = out_size / out_dim;       // out is (batch, out_dim)
    const int in_dim  = in_sizes[0] / batch;      // x is (batch, in_dim)

    const int npair = out_dim >> 1;
    precompute_kernel<<<(npair + 127) / 128, 128>>>(idx, w, out_dim);

    const size_t smem = (size_t)in_dim * ROWS * sizeof(__half);   // 64 KiB @ 4096
    const int grid = (batch + ROWS - 1) / ROWS;

    if (batch % ROWS == 0)
        launch_main_pdl<true>(x, out, in_dim, out_dim, batch, grid, smem);
    else
        launch_main_pdl<false>(x, out, in_dim, out_dim, batch, grid, smem);
}

// round 16
// speedup vs baseline: 1.1068x; 1.0684x over previous
#include <cuda_runtime.h>
#include <cuda_fp16.h>

// LogicDense: out[i][j] = c0 + c1*a + c2*b + c3*a*b
//   a = x[i, idx0[j]], b = x[i, idx1[j]]
//
// R16 = R13/R15 main kernel (at its compulsory-DRAM floor, 38.7 us across 4
// designs) + two gap-directed fixes informed by R15's neutral result:
//  1) cudaTriggerProgrammaticLaunchCompletion() moved to the TOP of
//     precompute: the trigger gates only the dependent LAUNCH, while
//     cudaGridDependencySynchronize() separately waits for completion. Early
//     trigger => main's staging (needs only x) fully overlaps precompute.
//  2) precompute parallelized to ONE COLUMN PER THREAD (8192 thr) with
//     bit-identical table layout (uint2/u32 writes alias the uint4/uint2
//     pair records) -> half the latency chain, consumer unchanged.

#define ROWS 8
#define THREADS 512
#define MAX_OUT 16384

__device__ uint4 g_cf[MAX_OUT / 2];   // pair view: h2(c0,c1)E, h2(c2,c3)E, h2(c0,c1)O, h2(c2,c3)O
__device__ uint2 g_of[MAX_OUT / 2];   // pair view: (offAE|offBE<<16, offAO|offBO<<16)

__constant__ float c_T[64] = {
    0.f, 0.f, 0.f, 0.f,
    0.f, 0.f, 0.f, 1.f,
    0.f, 1.f, 0.f,-1.f,
    0.f, 1.f, 0.f, 0.f,
    0.f, 0.f, 1.f,-1.f,
    0.f, 0.f, 1.f, 0.f,
    0.f, 1.f, 1.f,-2.f,
    0.f, 1.f, 1.f,-1.f,
    1.f,-1.f,-1.f, 1.f,
    1.f,-1.f,-1.f, 2.f,
    1.f, 0.f,-1.f, 0.f,
    1.f, 0.f,-1.f, 1.f,
    1.f,-1.f, 0.f, 0.f,
    1.f,-1.f, 0.f, 1.f,
    1.f, 0.f, 0.f,-1.f,
    1.f, 0.f, 0.f, 0.f
};

__device__ __forceinline__ int swz_off(int idx) {
    // half-index of the 8-row group of element idx in the swizzled tile
    return (idx << 3) ^ (((idx >> 3) & 7) << 3);
}

__global__ void precompute_kernel(const void* __restrict__ idx_raw,
                                  const float* __restrict__ w,
                                  int out_dim) {
    // Release the PDL launch dependency IMMEDIATELY: the dependent kernel's
    // staging phase is independent of the table; its compute loop is gated
    // by cudaGridDependencySynchronize(), which waits for this grid's
    // completion regardless of the trigger.
    cudaTriggerProgrammaticLaunchCompletion();

    // dtype detect: odd u32 words of the first 64 words are all zero iff the
    // buffer is int64 (high words of indices < in_dim). Warp-ballot, no smem.
    const unsigned int* u = (const unsigned int*)idx_raw;
    unsigned int probe = u[2 * (threadIdx.x & 31) + 1];
    const int is64 = !__any_sync(0xFFFFFFFFu, probe != 0u);

    int j = blockIdx.x * blockDim.x + threadIdx.x;   // column index
    if (j >= out_dim) return;

    const float4* w4 = (const float4*)(w + (size_t)j * 16);
    float4 wa = w4[0], wb = w4[1], wc = w4[2], wd = w4[3];
    float wv[16] = {wa.x, wa.y, wa.z, wa.w, wb.x, wb.y, wb.z, wb.w,
                    wc.x, wc.y, wc.z, wc.w, wd.x, wd.y, wd.z, wd.w};
    float m = -1e30f;
#pragma unroll
    for (int k = 0; k < 16; k++) m = fmaxf(m, wv[k]);
    float s = 0.f;
#pragma unroll
    for (int k = 0; k < 16; k++) {
        wv[k] = __expf(wv[k] - m);
        s += wv[k];
    }
    float inv = 1.f / s;
    float c0 = 0.f, c1 = 0.f, c2 = 0.f, c3 = 0.f;
#pragma unroll
    for (int k = 0; k < 16; k++) {
        float p = wv[k] * inv;
        c0 = fmaf(p, c_T[4 * k + 0], c0);
        c1 = fmaf(p, c_T[4 * k + 1], c1);
        c2 = fmaf(p, c_T[4 * k + 2], c2);
        c3 = fmaf(p, c_T[4 * k + 3], c3);
    }

    int i0, i1;
    if (is64) {
        const long long* p = (const long long*)idx_raw;
        i0 = (int)p[j];
        i1 = (int)p[out_dim + j];
    } else {
        const int* p = (const int*)idx_raw;
        i0 = p[j];
        i1 = p[out_dim + j];
    }

    // Per-column writes alias the pair-record layout exactly:
    //   uint2 cf2[j] = (h2(c0,c1), h2(c2,c3))  ==  halves of uint4 g_cf[j/2]
    //   u32   of2[j] = offA|offB<<16           ==  halves of uint2 g_of[j/2]
    __half2 c01 = __floats2half2_rn(c0, c1);
    __half2 c23 = __floats2half2_rn(c2, c3);
    uint2 cf2;
    cf2.x = *(unsigned int*)&c01;
    cf2.y = *(unsigned int*)&c23;
    ((uint2*)g_cf)[j] = cf2;
    ((unsigned int*)g_of)[j] =
        (unsigned int)swz_off(i0) | ((unsigned int)swz_off(i1) << 16);
}

__device__ __forceinline__ unsigned int pack_h2(float lo, float hi) {
    __half2 h = __floats2half2_rn(lo, hi);
    return *(unsigned int*)&h;
}

__device__ __forceinline__ float2 h22f2(unsigned int u) {
    return __half22float2(*(const __half2*)&u);
}

template <bool FULL>
__global__ __launch_bounds__(THREADS) void logic_main_kernel(
    const float* __restrict__ x,
    float* __restrict__ out,
    int in_dim, int out_dim, int batch) {
    extern __shared__ __half sh[];   // in_dim * 8 halfs (64 KiB @ 4096), swizzled

    const int rb = blockIdx.x * ROWS;
    const int nr = FULL ? ROWS : min(ROWS, batch - rb);

    // ---- stage 8 rows (independent of the table -> overlaps precompute) ----
    {
        const int n4 = in_dim >> 2;   // element-chunks of 4
        const float* xb = x + (size_t)rb * in_dim;
        for (int i = threadIdx.x; i < n4; i += blockDim.x) {
            float4 r[ROWS];
#pragma unroll
            for (int rr = 0; rr < ROWS; rr++) {
                int row = (FULL || rr < nr) ? rr : 0;
                r[rr] = *(const float4*)(xb + (size_t)row * in_dim + (i << 2));
            }
#pragma unroll
            for (int k = 0; k < 4; k++) {
                uint4 pk;
                pk.x = pack_h2((&r[0].x)[k], (&r[1].x)[k]);
                pk.y = pack_h2((&r[2].x)[k], (&r[3].x)[k]);
                pk.z = pack_h2((&r[4].x)[k], (&r[5].x)[k]);
                pk.w = pack_h2((&r[6].x)[k], (&r[7].x)[k]);
                const int idx = (i << 2) + k;
                *(uint4*)(sh + swz_off(idx)) = pk;
            }
        }
    }
    __syncthreads();

    // PDL: precompute's table writes must be visible before the compute loop.
    cudaGridDependencySynchronize();

    // ---- compute: column pair per thread, records prefetched 1 iter ahead ----
    const int npair = out_dim >> 1;
    int q = threadIdx.x;
    if (q < npair) {
        uint4 cf = g_cf[q];
        uint2 of = g_of[q];
        while (true) {
            const int qn = q + (int)blockDim.x;
            uint4 cfn; uint2 ofn;
            const bool more = (qn < npair);
            if (more) {             // prefetch next records before computing
                cfn = g_cf[qn];
                ofn = g_of[qn];
            }

            const uint4 aE = *(const uint4*)(sh + (of.x & 0xFFFFu));
            const uint4 bE = *(const uint4*)(sh + (of.x >> 16));
            const uint4 aO = *(const uint4*)(sh + (of.y & 0xFFFFu));
            const uint4 bO = *(const uint4*)(sh + (of.y >> 16));

            const float2 cE01 = h22f2(cf.x);
            const float2 cE23 = h22f2(cf.y);
            const float2 cO01 = h22f2(cf.z);
            const float2 cO23 = h22f2(cf.w);

            float* op = out + (size_t)rb * out_dim + 2 * q;
#pragma unroll
            for (int r2 = 0; r2 < 4; r2++) {
                const float2 vaE = h22f2((&aE.x)[r2]);
                const float2 vbE = h22f2((&bE.x)[r2]);
                const float2 vaO = h22f2((&aO.x)[r2]);
                const float2 vbO = h22f2((&bO.x)[r2]);

                // row 2*r2
                if (FULL || 2 * r2 < nr) {
                    float2 res;
                    res.x = fmaf(vaE.x, fmaf(vbE.x, cE23.y, cE01.y),
                                 fmaf(vbE.x, cE23.x, cE01.x));
                    res.y = fmaf(vaO.x, fmaf(vbO.x, cO23.y, cO01.y),
                                 fmaf(vbO.x, cO23.x, cO01.x));
                    *(float2*)(op + (size_t)(2 * r2) * out_dim) = res;
                }
                // row 2*r2+1
                if (FULL || 2 * r2 + 1 < nr) {
                    float2 res;
                    res.x = fmaf(vaE.y, fmaf(vbE.y, cE23.y, cE01.y),
                                 fmaf(vbE.y, cE23.x, cE01.x));
                    res.y = fmaf(vaO.y, fmaf(vbO.y, cO23.y, cO01.y),
                                 fmaf(vbO.y, cO23.x, cO01.x));
                    *(float2*)(op + (size_t)(2 * r2 + 1) * out_dim) = res;
                }
            }

            if (!more) break;
            q = qn;
            cf = cfn;
            of = ofn;
        }
    }
}

template <bool FULL>
static void launch_main_pdl(const float* x, float* out,
                            int in_dim, int out_dim, int batch,
                            int grid, size_t smem) {
    cudaFuncSetAttribute(logic_main_kernel<FULL>,
                         cudaFuncAttributeMaxDynamicSharedMemorySize, (int)smem);
    cudaLaunchConfig_t cfg = {};
    cfg.gridDim = dim3((unsigned)grid, 1, 1);
    cfg.blockDim = dim3(THREADS, 1, 1);
    cfg.dynamicSmemBytes = smem;
    cudaLaunchAttribute attr[1];
    attr[0].id = cudaLaunchAttributeProgrammaticStreamSerialization;
    attr[0].val.programmaticStreamSerializationAllowed = 1;
    cfg.attrs = attr;
    cfg.numAttrs = 1;
    cudaLaunchKernelEx(&cfg, logic_main_kernel<FULL>,
                       x, out, in_dim, out_dim, batch);
}

extern "C" void kernel_launch(void* const* d_in, const int* in_sizes, int n_in,
                              void* d_out, int out_size) {
    const float* x   = (const float*)d_in[0];
    const void*  idx = d_in[1];
    const float* w   = (const float*)d_in[2];
    float*       out = (float*)d_out;

    const int out_dim = in_sizes[2] / 16;         // weight is (out_dim, 16)
    const int batch   = out_size / out_dim;       // out is (batch, out_dim)
    const int in_dim  = in_sizes[0] / batch;      // x is (batch, in_dim)

    precompute_kernel<<<(out_dim + 127) / 128, 128>>>(idx, w, out_dim);

    const size_t smem = (size_t)in_dim * ROWS * sizeof(__half);   // 64 KiB @ 4096
    const int grid = (batch + ROWS - 1) / ROWS;

    if (batch % ROWS == 0)
        launch_main_pdl<true>(x, out, in_dim, out_dim, batch, grid, smem);
    else
        launch_main_pdl<false>(x, out, in_dim, out_dim, batch, grid, smem);
}